// round 13
// baseline (speedup 1.0000x reference)
#include <cuda_runtime.h>
#include <cuda_fp16.h>
#include <cstdint>

// ---------------------------------------------------------------------------
// Decoder_84731114815924  (B=4, N=256, D=32, H=512)
// R13: fp16 mma + warp-pair k-split GEMM2 (M=32/warp halves W2 LDS traffic),
// h1 A-frag exchange via smem + named pair barriers, z-frags via smem.
// ---------------------------------------------------------------------------

#define BNN   262144

__device__ uint32_t g_tmph[1024 * 16 * 512]; // 32 MB: per (bi,chk) GEMM1 B-frags
__device__ uint32_t g_w2h[16 * 4096];        // 256 KB: per-chk GEMM2 B-frags (uint4 tiles)
__device__ uint32_t g_zh[16384];             // 64 KB: GEMM1 A-frags

__device__ __forceinline__ uint32_t ph2(float a, float b) {
    __half2 h = __floats2half2_rn(a, b);
    return *(uint32_t*)&h;
}

#define MMA_F16(D, A, B0, B1)                                               \
    asm volatile(                                                           \
        "mma.sync.aligned.m16n8k16.row.col.f32.f16.f16.f32 "                \
        "{%0,%1,%2,%3}, {%4,%5,%6,%7}, {%8,%9}, {%0,%1,%2,%3};\n"           \
        : "+f"(D[0]), "+f"(D[1]), "+f"(D[2]), "+f"(D[3])                    \
        : "r"(A[0]), "r"(A[1]), "r"(A[2]), "r"(A[3]), "r"(B0), "r"(B1))

__device__ __forceinline__ void cp16(uint32_t s, const void* g) {
    asm volatile("cp.async.cg.shared.global [%0], [%1], 16;" :: "r"(s), "l"(g));
}
__device__ __forceinline__ void cp_commit() { asm volatile("cp.async.commit_group;"); }
__device__ __forceinline__ void cp_wait0()  { asm volatile("cp.async.wait_group 0;"); }

// ---------------------------------------------------------------------------
// Stage A: tmp[bi][c][h] = sum_a z[bi][a] * W1[a*16384 + c*512 + h], emitted
// as fp16 GEMM1 B-fragments:
//   u32 idx = (bi*16+chk)*512 + ((ntile*2+s)*2+bh)*32 + lane,
//   val = {tmp[c][h], tmp[c+1][h]},  h = chk*32+ntile*8+(lane>>2),
//                                    c = s*16+bh*8+(lane&3)*2.
// ---------------------------------------------------------------------------
__global__ __launch_bounds__(256) void stage_a_kernel(
    const float* __restrict__ z, const float* __restrict__ W1)
{
    __shared__ float zt[64][33];
    __shared__ float wt[32][132];
    const int oct = blockIdx.x & 3;
    const int hg  = blockIdx.x >> 2;
    const int bi0 = blockIdx.y * 64;
    const int c0  = oct * 8, h0 = hg * 16;
    const int tid = threadIdx.x;

    for (int idx = tid; idx < 64 * 32; idx += 256) {
        int r = idx >> 5, a = idx & 31;
        zt[r][a] = z[(bi0 + r) * 32 + a];
    }
    for (int idx = tid; idx < 32 * 128; idx += 256) {
        int a = idx >> 7, col = idx & 127;
        int ci = col >> 4, hi = col & 15;
        wt[a][col] = W1[a * 16384 + (c0 + ci) * 512 + h0 + hi];
    }
    __syncthreads();

    const int tm = tid >> 4;
    const int tn = tid & 15;

    float acc[4][8];
#pragma unroll
    for (int i = 0; i < 4; i++)
#pragma unroll
        for (int j = 0; j < 8; j++) acc[i][j] = 0.f;

#pragma unroll
    for (int k = 0; k < 32; k++) {
        float a[4], bb[8];
#pragma unroll
        for (int i = 0; i < 4; i++) a[i] = zt[tm * 4 + i][k];
#pragma unroll
        for (int j = 0; j < 8; j++) bb[j] = wt[k][j * 16 + tn];
#pragma unroll
        for (int i = 0; i < 4; i++)
#pragma unroll
            for (int j = 0; j < 8; j++) acc[i][j] = fmaf(a[i], bb[j], acc[i][j]);
    }

    const int h   = h0 + tn;
    const int chk = h >> 5;
    const int nt  = (h >> 3) & 3;
    const int g   = h & 7;
    const int s   = oct >> 1, bh = oct & 1;
#pragma unroll
    for (int i = 0; i < 4; i++) {
        const int bi = bi0 + tm * 4 + i;
        uint4 v;
        v.x = ph2(acc[i][0], acc[i][1]);
        v.y = ph2(acc[i][2], acc[i][3]);
        v.z = ph2(acc[i][4], acc[i][5]);
        v.w = ph2(acc[i][6], acc[i][7]);
        ((uint4*)g_tmph)[(size_t)(bi * 16 + chk) * 128 + ((nt * 2 + s) * 2 + bh) * 8 + g] = v;
    }
}

// ---------------------------------------------------------------------------
// Pack W2 -> fp16 GEMM2 B-frags, uint4-tile layout:
//   u32 idx = chk*4096 + nt*128 + lane*4 + s*2 + bh
//   val = {W2[h][k2], W2[h+1][k2]},
//   h = chk*32 + s*16 + bh*8 + (lane&3)*2,  k2 = nt*8 + (lane>>2)
// ---------------------------------------------------------------------------
__global__ __launch_bounds__(256) void pack_w2_kernel(const float* __restrict__ W2)
{
    const int gid  = blockIdx.x * 256 + threadIdx.x;   // 65536
    const int bh   = gid & 1;
    const int s    = (gid >> 1) & 1;
    const int lane = (gid >> 2) & 31;
    const int nt   = (gid >> 7) & 31;
    const int chk  = gid >> 12;
    const int h  = chk * 32 + s * 16 + bh * 8 + (lane & 3) * 2;
    const int k2 = nt * 8 + (lane >> 2);
    g_w2h[gid] = ph2(W2[h * 256 + k2], W2[(h + 1) * 256 + k2]);
}

// ---------------------------------------------------------------------------
// Pack z -> fp16 GEMM1 A-frags: u32 idx = (tile*2+s)*128 + lane*4 + r
// ---------------------------------------------------------------------------
__global__ __launch_bounds__(256) void pack_z_kernel(const float* __restrict__ z)
{
    const int gid  = blockIdx.x * 256 + threadIdx.x;   // 16384
    const int r    = gid & 3;
    const int lane = (gid >> 2) & 31;
    const int s    = (gid >> 7) & 1;
    const int tile = gid >> 8;
    const int g = lane >> 2, t = lane & 3;
    const int row = tile * 16 + g + (r & 1) * 8;
    const int col = s * 16 + t * 2 + (r >> 1) * 8;
    g_zh[gid] = ph2(z[row * 32 + col], z[row * 32 + col + 1]);
}

// ---------------------------------------------------------------------------
// Main fused kernel: grid 4096 = (b, i, jt of 4), 128 threads, 3 CTAs/SM.
// Warp w: GEMM1 owns j-tile w (16 rows). GEMM2: j-tiles {w, w^1} (32 rows)
// x k-half (w&1) -> W2 chunk read by 2 half-reads instead of 4 full reads.
// h1 A-frags exchanged via smem (double-buffered) + named pair barrier.
// smem u32: tmp 2x512 @0; w2 2x4096 @1024; b1 @9216; b2 @9728; w3 @9984;
//           h1s 2x1024 @10240; zsm 1024 @12288; red(f32,128) @13312.
// ---------------------------------------------------------------------------
#define SMO_H1  10240
#define SMO_Z   12288
#define SMO_RED 13312
#define SM_TOT  13440          // floats = 53760 bytes

__global__ __launch_bounds__(128, 3) void decoder_main_kernel(
    const float* __restrict__ motif,
    const float* __restrict__ b1, const float* __restrict__ b2,
    const float* __restrict__ W3, const float* __restrict__ b3,
    float* __restrict__ out)
{
    extern __shared__ float sm[];
    uint32_t* smu = (uint32_t*)sm;
    const uint32_t s_u32 = (uint32_t)__cvta_generic_to_shared(sm);
    float* s_b1 = sm + 9216;
    float* s_b2 = sm + 9728;
    float* s_w3 = sm + 9984;
    float* s_red = sm + SMO_RED;

    const int cta = blockIdx.x;
    const int jt  = cta & 3;
    const int i   = (cta >> 2) & 255;
    const int b   = cta >> 10;
    const int bi  = b * 256 + i;
    const int j0  = jt * 64;

    const int tid  = threadIdx.x;
    const int w    = tid >> 5;
    const int lane = tid & 31;
    const int g    = lane >> 2;
    const int t    = lane & 3;
    const int kh   = w & 1;          // k-half for GEMM2
    const int barid = (w >> 1) + 1;  // pair barrier id

    // ---- prologue: async loads of chunk 0 + z-frags ----------------------
    {
        const uint4* wsrc = (const uint4*)g_w2h;
#pragma unroll
        for (int r = 0; r < 8; r++)
            cp16(s_u32 + (1024 + (tid + r * 128) * 4) * 4, wsrc + tid + r * 128);
        const uint4* tsrc = (const uint4*)g_tmph + (size_t)bi * 16 * 128;
        cp16(s_u32 + (tid * 4) * 4, tsrc + tid);
        const uint4* zsrc = (const uint4*)g_zh + (size_t)(b * 16 + jt * 4) * 64;
        cp16(s_u32 + (SMO_Z + tid * 4) * 4, zsrc + tid);
        cp16(s_u32 + (SMO_Z + (tid + 128) * 4) * 4, zsrc + tid + 128);
        cp_commit();
    }
    for (int idx = tid; idx < 1024; idx += 128) {
        if (idx < 512)       s_b1[idx] = b1[idx];
        else if (idx < 768)  s_b2[idx - 512] = b2[idx - 512];
        else                 s_w3[idx - 768] = W3[idx - 768];
    }

    float acc2[2][16][4];
#pragma unroll
    for (int mt = 0; mt < 2; mt++)
#pragma unroll
        for (int nt = 0; nt < 16; nt++)
#pragma unroll
            for (int r = 0; r < 4; r++) acc2[mt][nt][r] = 0.f;

    int buf = 0;
    for (int chk = 0; chk < 16; chk++) {
        const int ph = chk & 1;
        cp_wait0();
        __syncthreads();

        if (chk < 15) {
            const int nb = buf ^ 1;
            const uint4* wsrc = (const uint4*)g_w2h + (chk + 1) * 1024;
#pragma unroll
            for (int r = 0; r < 8; r++)
                cp16(s_u32 + (1024 + nb * 4096 + (tid + r * 128) * 4) * 4,
                     wsrc + tid + r * 128);
            const uint4* tsrc = (const uint4*)g_tmph + ((size_t)bi * 16 + chk + 1) * 128;
            cp16(s_u32 + (nb * 512 + tid * 4) * 4, tsrc + tid);
            cp_commit();
        }

        const uint32_t* tb = smu + buf * 512;
        const uint32_t* wb = smu + 1024 + buf * 4096;

        // ---- z A-frags from smem (frees persistent registers) -----------
        uint4 z0 = *(const uint4*)&smu[SMO_Z + (w * 2 + 0) * 128 + lane * 4];
        uint4 z1 = *(const uint4*)&smu[SMO_Z + (w * 2 + 1) * 128 + lane * 4];
        uint32_t za0[4] = { z0.x, z0.y, z0.z, z0.w };
        uint32_t za1[4] = { z1.x, z1.y, z1.z, z1.w };

        // ---- GEMM1: acc1 = z_tile(w) . tmp^T  (16j x 32h) ----------------
        float acc1[4][4];
#pragma unroll
        for (int nt = 0; nt < 4; nt++)
#pragma unroll
            for (int r = 0; r < 4; r++) acc1[nt][r] = 0.f;

#pragma unroll
        for (int nt = 0; nt < 4; nt++) {
            {
                uint32_t b0 = tb[((nt * 2 + 0) * 2 + 0) * 32 + lane];
                uint32_t bb = tb[((nt * 2 + 0) * 2 + 1) * 32 + lane];
                MMA_F16(acc1[nt], za0, b0, bb);
            }
            {
                uint32_t b0 = tb[((nt * 2 + 1) * 2 + 0) * 32 + lane];
                uint32_t bb = tb[((nt * 2 + 1) * 2 + 1) * 32 + lane];
                MMA_F16(acc1[nt], za1, b0, bb);
            }
        }

        // bias + relu + fp16 pack -> own A-frags
        uint32_t h1h[4][2];
#pragma unroll
        for (int nt = 0; nt < 4; nt++) {
            const float* bb = s_b1 + chk * 32 + nt * 8 + t * 2;
            float v0 = fmaxf(acc1[nt][0] + bb[0], 0.f);
            float v1 = fmaxf(acc1[nt][1] + bb[1], 0.f);
            float v2 = fmaxf(acc1[nt][2] + bb[0], 0.f);
            float v3 = fmaxf(acc1[nt][3] + bb[1], 0.f);
            h1h[nt][0] = ph2(v0, v1);
            h1h[nt][1] = ph2(v2, v3);
        }

        // ---- exchange h1 A-frags with partner warp (w^1) -----------------
        const uint32_t hb = SMO_H1 + (ph * 4 + w) * 256;
        uint4 own0 = { h1h[0][0], h1h[0][1], h1h[1][0], h1h[1][1] };
        uint4 own1 = { h1h[2][0], h1h[2][1], h1h[3][0], h1h[3][1] };
        *(uint4*)&smu[hb + lane * 4]       = own0;
        *(uint4*)&smu[hb + 128 + lane * 4] = own1;
        asm volatile("bar.sync %0, 64;" :: "r"(barid) : "memory");
        const uint32_t pb = SMO_H1 + (ph * 4 + (w ^ 1)) * 256;
        uint4 P0 = *(const uint4*)&smu[pb + lane * 4];
        uint4 P1 = *(const uint4*)&smu[pb + 128 + lane * 4];

        uint32_t A0[4]  = { own0.x, own0.y, own0.z, own0.w };
        uint32_t A1[4]  = { own1.x, own1.y, own1.z, own1.w };
        uint32_t PA0[4] = { P0.x, P0.y, P0.z, P0.w };
        uint32_t PA1[4] = { P1.x, P1.y, P1.z, P1.w };

        // ---- GEMM2: 32j x 128k2 (k-half kh), B loaded once ---------------
#pragma unroll
        for (int nt = 0; nt < 16; nt++) {
            uint4 bv = *(const uint4*)&wb[(kh * 16 + nt) * 128 + lane * 4];
            MMA_F16(acc2[0][nt], A0,  bv.x, bv.y);
            MMA_F16(acc2[0][nt], A1,  bv.z, bv.w);
            MMA_F16(acc2[1][nt], PA0, bv.x, bv.y);
            MMA_F16(acc2[1][nt], PA1, bv.z, bv.w);
        }
        buf ^= 1;
    }

    // ---- epilogue: relu(+b2) . W3 over k-half, pair-combine via smem -----
#pragma unroll
    for (int mt = 0; mt < 2; mt++) {
        float ps0 = 0.f, ps1 = 0.f;
#pragma unroll
        for (int nt = 0; nt < 16; nt++) {
            const int k = (kh * 16 + nt) * 8 + t * 2;
            float h2a = fmaxf(acc2[mt][nt][0] + s_b2[k],     0.f);
            float h2b = fmaxf(acc2[mt][nt][1] + s_b2[k + 1], 0.f);
            float h2c = fmaxf(acc2[mt][nt][2] + s_b2[k],     0.f);
            float h2d = fmaxf(acc2[mt][nt][3] + s_b2[k + 1], 0.f);
            ps0 = fmaf(h2a, s_w3[k], ps0);  ps0 = fmaf(h2b, s_w3[k + 1], ps0);
            ps1 = fmaf(h2c, s_w3[k], ps1);  ps1 = fmaf(h2d, s_w3[k + 1], ps1);
        }
        ps0 += __shfl_xor_sync(0xffffffffu, ps0, 1);
        ps0 += __shfl_xor_sync(0xffffffffu, ps0, 2);
        ps1 += __shfl_xor_sync(0xffffffffu, ps1, 1);
        ps1 += __shfl_xor_sync(0xffffffffu, ps1, 2);
        if (t == 0) {
            const int tile = mt ? (w ^ 1) : w;
            s_red[(tile * 16 + g) * 2 + kh]     = ps0;
            s_red[(tile * 16 + g + 8) * 2 + kh] = ps1;
        }
    }
    __syncthreads();

    if (tid < 64) {
        float logit = s_red[tid * 2] + s_red[tid * 2 + 1] + b3[0];
        float mask  = motif[b * 256 + i] * motif[b * 256 + j0 + tid];
        logit *= mask;
        float cmap = 1.f / (1.f + __expf(-logit));
        size_t base = (size_t)bi * 256 + j0 + tid;
        out[base]       = cmap;
        out[BNN + base] = logit;
    }
}

// ---------------------------------------------------------------------------
extern "C" void kernel_launch(void* const* d_in, const int* in_sizes, int n_in,
                              void* d_out, int out_size)
{
    const float* z     = (const float*)d_in[0];
    const float* motif = (const float*)d_in[1];
    const float* W1    = (const float*)d_in[3];
    const float* b1    = (const float*)d_in[4];
    const float* W2    = (const float*)d_in[5];
    const float* b2    = (const float*)d_in[6];
    const float* W3    = (const float*)d_in[7];
    const float* b3    = (const float*)d_in[8];
    float* out = (float*)d_out;

    (void)in_sizes; (void)n_in; (void)out_size;

    cudaFuncSetAttribute(decoder_main_kernel,
                         cudaFuncAttributeMaxDynamicSharedMemorySize,
                         SM_TOT * (int)sizeof(float));

    stage_a_kernel<<<dim3(128, 16), 256>>>(z, W1);
    pack_w2_kernel<<<256, 256>>>(W2);
    pack_z_kernel<<<64, 256>>>(z);
    decoder_main_kernel<<<4096, 128, SM_TOT * sizeof(float)>>>(
        motif, b1, b2, W3, b3, out);
}

// round 14
// speedup vs baseline: 1.0334x; 1.0334x over previous
#include <cuda_runtime.h>
#include <cuda_fp16.h>
#include <cstdint>

// ---------------------------------------------------------------------------
// Decoder_84731114815924  (B=4, N=256, D=32, H=512)
// R14: main kernel = R12 (best known: fp16 mma, 3 CTAs/SM, uint4 B-frags).
// Stage-A rewritten: 4bi x 8c x 2h thread tiles + k-major broadcast z loads
// (fewer LDS per FMA). Identical numerics to R12.
// ---------------------------------------------------------------------------

#define BNN   262144

__device__ uint32_t g_tmph[1024 * 16 * 512]; // 32 MB: per (bi,chk) GEMM1 B-frags
__device__ uint32_t g_w2h[16 * 4096];        // 256 KB: per-chk GEMM2 B-frags (uint4 tiles)
__device__ uint32_t g_zh[16384];             // 64 KB: GEMM1 A-frags

__device__ __forceinline__ uint32_t ph2(float a, float b) {
    __half2 h = __floats2half2_rn(a, b);
    return *(uint32_t*)&h;
}

#define MMA_F16(D, A, B0, B1)                                               \
    asm volatile(                                                           \
        "mma.sync.aligned.m16n8k16.row.col.f32.f16.f16.f32 "                \
        "{%0,%1,%2,%3}, {%4,%5,%6,%7}, {%8,%9}, {%0,%1,%2,%3};\n"           \
        : "+f"(D[0]), "+f"(D[1]), "+f"(D[2]), "+f"(D[3])                    \
        : "r"(A[0]), "r"(A[1]), "r"(A[2]), "r"(A[3]), "r"(B0), "r"(B1))

__device__ __forceinline__ void cp16(uint32_t s, const void* g) {
    asm volatile("cp.async.cg.shared.global [%0], [%1], 16;" :: "r"(s), "l"(g));
}
__device__ __forceinline__ void cp_commit() { asm volatile("cp.async.commit_group;"); }
__device__ __forceinline__ void cp_wait0()  { asm volatile("cp.async.wait_group 0;"); }

// ---------------------------------------------------------------------------
// Stage A v2: tmp[bi][c][h] = sum_a z[bi][a] * W1[a*16384 + c*512 + h]
// emitted as fp16 GEMM1 B-fragments (same layout/values as before):
//   u32 idx = (bi*16+chk)*512 + ((ntile*2+s)*2+bh)*32 + lane,
//   val = {tmp[c][h], tmp[c+1][h]},  h = chk*32+ntile*8+(lane>>2),
//                                    c = s*16+bh*8+(lane&3)*2.
// Block: 64 bi x 8 c (oct) x 32 h. Thread: 4 bi x 8 c x 2 h (64 FMA/k).
// z staged k-major (broadcast LDS.128); W1 tile conflict-free scalar LDS.
// ---------------------------------------------------------------------------
__global__ __launch_bounds__(256) void stage_a_kernel(
    const float* __restrict__ z, const float* __restrict__ W1)
{
    __shared__ float zt[32][68];     // [a][bi_local]
    __shared__ float wt[32][264];    // [a][ci*32 + hi]
    const int oct = blockIdx.x & 3;        // c0 = oct*8
    const int hg  = blockIdx.x >> 2;       // h0 = hg*32
    const int bi0 = blockIdx.y * 64;
    const int c0  = oct * 8, h0 = hg * 32;
    const int tid = threadIdx.x;

    // fill z transposed: zt[a][r] = z[bi0+r][a]
    for (int idx = tid; idx < 64 * 32; idx += 256) {
        int r = idx >> 5, a = idx & 31;
        zt[a][r] = z[(bi0 + r) * 32 + a];
    }
    // fill W1 tile: wt[a][ci*32+hi] = W1[a][ (c0+ci)*512 + h0+hi ]
    for (int idx = tid; idx < 32 * 256; idx += 256) {
        int a = idx >> 8, col = idx & 255;
        int ci = col >> 5, hi = col & 31;
        wt[a][col] = W1[a * 16384 + (c0 + ci) * 512 + h0 + hi];
    }
    __syncthreads();

    const int tm = tid >> 4;   // 16 groups of 4 bi
    const int tn = tid & 15;   // h pair: {h0+tn, h0+tn+16}

    float acc[2][4][8];        // [uh][bi][c]
#pragma unroll
    for (int u = 0; u < 2; u++)
#pragma unroll
        for (int i = 0; i < 4; i++)
#pragma unroll
            for (int j = 0; j < 8; j++) acc[u][i][j] = 0.f;

#pragma unroll
    for (int k = 0; k < 32; k++) {
        float4 a4 = *(const float4*)&zt[k][tm * 4];
        float av[4] = { a4.x, a4.y, a4.z, a4.w };
        float b0[8], b1[8];
#pragma unroll
        for (int j = 0; j < 8; j++) {
            b0[j] = wt[k][j * 32 + tn];
            b1[j] = wt[k][j * 32 + tn + 16];
        }
#pragma unroll
        for (int i = 0; i < 4; i++)
#pragma unroll
            for (int j = 0; j < 8; j++) {
                acc[0][i][j] = fmaf(av[i], b0[j], acc[0][i][j]);
                acc[1][i][j] = fmaf(av[i], b1[j], acc[1][i][j]);
            }
    }

    const int s = oct >> 1, bh = oct & 1;
#pragma unroll
    for (int u = 0; u < 2; u++) {
        const int h   = h0 + tn + u * 16;
        const int chk = h >> 5;
        const int nt  = (h >> 3) & 3;
        const int g   = h & 7;
#pragma unroll
        for (int i = 0; i < 4; i++) {
            const int bi = bi0 + tm * 4 + i;
            uint4 v;
            v.x = ph2(acc[u][i][0], acc[u][i][1]);
            v.y = ph2(acc[u][i][2], acc[u][i][3]);
            v.z = ph2(acc[u][i][4], acc[u][i][5]);
            v.w = ph2(acc[u][i][6], acc[u][i][7]);
            ((uint4*)g_tmph)[(size_t)(bi * 16 + chk) * 128 + ((nt * 2 + s) * 2 + bh) * 8 + g] = v;
        }
    }
}

// ---------------------------------------------------------------------------
// Pack W2 -> fp16 GEMM2 B-frags, uint4-tile layout:
//   u32 idx = chk*4096 + nt*128 + lane*4 + s*2 + bh
//   val = {W2[h][k2], W2[h+1][k2]},
//   h = chk*32 + s*16 + bh*8 + (lane&3)*2,  k2 = nt*8 + (lane>>2)
// ---------------------------------------------------------------------------
__global__ __launch_bounds__(256) void pack_w2_kernel(const float* __restrict__ W2)
{
    const int gid  = blockIdx.x * 256 + threadIdx.x;   // 65536
    const int bh   = gid & 1;
    const int s    = (gid >> 1) & 1;
    const int lane = (gid >> 2) & 31;
    const int nt   = (gid >> 7) & 31;
    const int chk  = gid >> 12;
    const int h  = chk * 32 + s * 16 + bh * 8 + (lane & 3) * 2;
    const int k2 = nt * 8 + (lane >> 2);
    g_w2h[gid] = ph2(W2[h * 256 + k2], W2[(h + 1) * 256 + k2]);
}

// ---------------------------------------------------------------------------
// Pack z -> fp16 GEMM1 A-frags: u32 idx = (tile*2+s)*128 + lane*4 + r
// ---------------------------------------------------------------------------
__global__ __launch_bounds__(256) void pack_z_kernel(const float* __restrict__ z)
{
    const int gid  = blockIdx.x * 256 + threadIdx.x;   // 16384
    const int r    = gid & 3;
    const int lane = (gid >> 2) & 31;
    const int s    = (gid >> 7) & 1;
    const int tile = gid >> 8;
    const int g = lane >> 2, t = lane & 3;
    const int row = tile * 16 + g + (r & 1) * 8;
    const int col = s * 16 + t * 2 + (r >> 1) * 8;
    g_zh[gid] = ph2(z[row * 32 + col], z[row * 32 + col + 1]);
}

// ---------------------------------------------------------------------------
// Main fused kernel (R12): grid 4096 = (b, i, jt of 4), 128 thr, 3 CTAs/SM.
// Warp w owns j rows [w*16, w*16+16) end-to-end:
//   GEMM1: 16j x 32h chunk (8 MMAs), C-frag -> relu+bias -> fp16 A-frag (regs)
//   GEMM2: 16j x 256k2, one uint4 B load per nt (32 LDS.128), acc2[32][4] fp32.
// smem u32: tmp 2x512 @0, w2 2x4096 @1024; floats: b1@9216 b2@9728 w3@9984.
// ---------------------------------------------------------------------------
#define SM_TOT  10240          // floats = 40960 bytes

__global__ __launch_bounds__(128, 3) void decoder_main_kernel(
    const float* __restrict__ motif,
    const float* __restrict__ b1, const float* __restrict__ b2,
    const float* __restrict__ W3, const float* __restrict__ b3,
    float* __restrict__ out)
{
    extern __shared__ float sm[];
    uint32_t* smu = (uint32_t*)sm;
    const uint32_t s_u32 = (uint32_t)__cvta_generic_to_shared(sm);
    float* s_b1 = sm + 9216;
    float* s_b2 = sm + 9728;
    float* s_w3 = sm + 9984;

    const int cta = blockIdx.x;
    const int jt  = cta & 3;
    const int i   = (cta >> 2) & 255;
    const int b   = cta >> 10;
    const int bi  = b * 256 + i;
    const int j0  = jt * 64;

    const int tid  = threadIdx.x;
    const int w    = tid >> 5;
    const int lane = tid & 31;
    const int g    = lane >> 2;
    const int t    = lane & 3;

    // ---- z A-frags, register-resident (chunk-invariant) ------------------
    uint32_t za[2][4];
    {
        const int tile = ((b * 256 + j0) >> 4) + w;
        const uint4* zf = (const uint4*)g_zh;
#pragma unroll
        for (int s = 0; s < 2; s++) {
            uint4 v = zf[(tile * 2 + s) * 32 + lane];
            za[s][0] = v.x; za[s][1] = v.y; za[s][2] = v.z; za[s][3] = v.w;
        }
    }

    // ---- prologue: async loads of chunk 0 --------------------------------
    {
        const uint4* wsrc = (const uint4*)g_w2h;
#pragma unroll
        for (int r = 0; r < 8; r++)
            cp16(s_u32 + (1024 + (tid + r * 128) * 4) * 4, wsrc + tid + r * 128);
        const uint4* tsrc = (const uint4*)g_tmph + (size_t)bi * 16 * 128;
        cp16(s_u32 + (tid * 4) * 4, tsrc + tid);
        cp_commit();
    }
    for (int idx = tid; idx < 1024; idx += 128) {
        if (idx < 512)       s_b1[idx] = b1[idx];
        else if (idx < 768)  s_b2[idx - 512] = b2[idx - 512];
        else                 s_w3[idx - 768] = W3[idx - 768];
    }

    float acc2[32][4];
#pragma unroll
    for (int nt = 0; nt < 32; nt++)
#pragma unroll
        for (int r = 0; r < 4; r++) acc2[nt][r] = 0.f;

    int buf = 0;
    for (int chk = 0; chk < 16; chk++) {
        cp_wait0();
        __syncthreads();

        if (chk < 15) {
            const int nb = buf ^ 1;
            const uint4* wsrc = (const uint4*)g_w2h + (chk + 1) * 1024;
#pragma unroll
            for (int r = 0; r < 8; r++)
                cp16(s_u32 + (1024 + nb * 4096 + (tid + r * 128) * 4) * 4,
                     wsrc + tid + r * 128);
            const uint4* tsrc = (const uint4*)g_tmph + ((size_t)bi * 16 + chk + 1) * 128;
            cp16(s_u32 + (nb * 512 + tid * 4) * 4, tsrc + tid);
            cp_commit();
        }

        const uint32_t* tb = smu + buf * 512;
        const uint32_t* wb = smu + 1024 + buf * 4096;

        // ---- GEMM1: acc1 = z_rows(w) . tmp^T  (16j x 32h) ----------------
        float acc1[4][4];
#pragma unroll
        for (int nt = 0; nt < 4; nt++)
#pragma unroll
            for (int r = 0; r < 4; r++) acc1[nt][r] = 0.f;

#pragma unroll
        for (int s = 0; s < 2; s++)
#pragma unroll
            for (int nt = 0; nt < 4; nt++) {
                uint32_t b0 = tb[((nt * 2 + s) * 2 + 0) * 32 + lane];
                uint32_t bb = tb[((nt * 2 + s) * 2 + 1) * 32 + lane];
                MMA_F16(acc1[nt], za[s], b0, bb);
            }

        // bias + relu + fp16 pack: C-frag -> A-frag, all in registers
        uint32_t h1h[4][2];
#pragma unroll
        for (int nt = 0; nt < 4; nt++) {
            const float* bb = s_b1 + chk * 32 + nt * 8 + t * 2;
            float v0 = fmaxf(acc1[nt][0] + bb[0], 0.f);
            float v1 = fmaxf(acc1[nt][1] + bb[1], 0.f);
            float v2 = fmaxf(acc1[nt][2] + bb[0], 0.f);
            float v3 = fmaxf(acc1[nt][3] + bb[1], 0.f);
            h1h[nt][0] = ph2(v0, v1);
            h1h[nt][1] = ph2(v2, v3);
        }

        // ---- GEMM2: acc2 += h1(16j) . W2chunk (256 k2) -------------------
        {
            uint32_t A0[4] = { h1h[0][0], h1h[0][1], h1h[1][0], h1h[1][1] };
            uint32_t A1[4] = { h1h[2][0], h1h[2][1], h1h[3][0], h1h[3][1] };
#pragma unroll
            for (int nt = 0; nt < 32; nt++) {
                uint4 bv = *(const uint4*)&wb[nt * 128 + lane * 4];
                MMA_F16(acc2[nt], A0, bv.x, bv.y);
                MMA_F16(acc2[nt], A1, bv.z, bv.w);
            }
        }
        buf ^= 1;
    }

    // ---- epilogue: relu(+b2) . W3 (full k2 in-warp), quad-reduce ---------
    float ps0 = 0.f, ps1 = 0.f;
#pragma unroll
    for (int nt = 0; nt < 32; nt++) {
        const int k = nt * 8 + t * 2;
        float h2a = fmaxf(acc2[nt][0] + s_b2[k],     0.f);
        float h2b = fmaxf(acc2[nt][1] + s_b2[k + 1], 0.f);
        float h2c = fmaxf(acc2[nt][2] + s_b2[k],     0.f);
        float h2d = fmaxf(acc2[nt][3] + s_b2[k + 1], 0.f);
        ps0 = fmaf(h2a, s_w3[k], ps0);  ps0 = fmaf(h2b, s_w3[k + 1], ps0);
        ps1 = fmaf(h2c, s_w3[k], ps1);  ps1 = fmaf(h2d, s_w3[k + 1], ps1);
    }
    ps0 += __shfl_xor_sync(0xffffffffu, ps0, 1);
    ps0 += __shfl_xor_sync(0xffffffffu, ps0, 2);
    ps1 += __shfl_xor_sync(0xffffffffu, ps1, 1);
    ps1 += __shfl_xor_sync(0xffffffffu, ps1, 2);

    if (t == 0) {
        const float b3v = b3[0];
        const float mi  = motif[b * 256 + i];
#pragma unroll
        for (int u = 0; u < 2; u++) {
            const int j = j0 + w * 16 + g + u * 8;
            float logit = ((u ? ps1 : ps0) + b3v) * (mi * motif[b * 256 + j]);
            float cmap  = 1.f / (1.f + __expf(-logit));
            size_t base = (size_t)bi * 256 + j;
            out[base]       = cmap;
            out[BNN + base] = logit;
        }
    }
}

// ---------------------------------------------------------------------------
extern "C" void kernel_launch(void* const* d_in, const int* in_sizes, int n_in,
                              void* d_out, int out_size)
{
    const float* z     = (const float*)d_in[0];
    const float* motif = (const float*)d_in[1];
    const float* W1    = (const float*)d_in[3];
    const float* b1    = (const float*)d_in[4];
    const float* W2    = (const float*)d_in[5];
    const float* b2    = (const float*)d_in[6];
    const float* W3    = (const float*)d_in[7];
    const float* b3    = (const float*)d_in[8];
    float* out = (float*)d_out;

    (void)in_sizes; (void)n_in; (void)out_size;

    cudaFuncSetAttribute(decoder_main_kernel,
                         cudaFuncAttributeMaxDynamicSharedMemorySize,
                         SM_TOT * (int)sizeof(float));

    stage_a_kernel<<<dim3(64, 16), 256>>>(z, W1);
    pack_w2_kernel<<<256, 256>>>(W2);
    pack_z_kernel<<<64, 256>>>(z);
    decoder_main_kernel<<<4096, 128, SM_TOT * sizeof(float)>>>(
        motif, b1, b2, W3, b3, out);
}

// round 15
// speedup vs baseline: 1.6315x; 1.5787x over previous
#include <cuda_runtime.h>
#include <cuda_fp16.h>
#include <cstdint>

// ---------------------------------------------------------------------------
// Decoder_84731114815924  (B=4, N=256, D=32, H=512)
// R15: R12 main kernel + GEMM2 dependency-pair interleaving (dependent HMMAs
// 2 apart instead of back-to-back) + single merged preprocessing launch.
// ---------------------------------------------------------------------------

#define BNN   262144

__device__ uint32_t g_tmph[1024 * 16 * 512]; // 32 MB: per (bi,chk) GEMM1 B-frags
__device__ uint32_t g_w2h[16 * 4096];        // 256 KB: per-chk GEMM2 B-frags (uint4 tiles)
__device__ uint32_t g_zh[16384];             // 64 KB: GEMM1 A-frags

__device__ __forceinline__ uint32_t ph2(float a, float b) {
    __half2 h = __floats2half2_rn(a, b);
    return *(uint32_t*)&h;
}

#define MMA_F16(D, A, B0, B1)                                               \
    asm volatile(                                                           \
        "mma.sync.aligned.m16n8k16.row.col.f32.f16.f16.f32 "                \
        "{%0,%1,%2,%3}, {%4,%5,%6,%7}, {%8,%9}, {%0,%1,%2,%3};\n"           \
        : "+f"(D[0]), "+f"(D[1]), "+f"(D[2]), "+f"(D[3])                    \
        : "r"(A[0]), "r"(A[1]), "r"(A[2]), "r"(A[3]), "r"(B0), "r"(B1))

__device__ __forceinline__ void cp16(uint32_t s, const void* g) {
    asm volatile("cp.async.cg.shared.global [%0], [%1], 16;" :: "r"(s), "l"(g));
}
__device__ __forceinline__ void cp_commit() { asm volatile("cp.async.commit_group;"); }
__device__ __forceinline__ void cp_wait0()  { asm volatile("cp.async.wait_group 0;"); }

// ---------------------------------------------------------------------------
// Merged preprocessing kernel, 1344 blocks x 256 threads:
//   blocks [0,1024): stage-A  (tmp GEMM -> fp16 GEMM1 B-frags)
//   blocks [1024,1280): pack W2 -> fp16 GEMM2 B-frags (uint4-tile layout)
//   blocks [1280,1344): pack z -> fp16 GEMM1 A-frags
// Layouts identical to R12/R14 (bit-identical outputs).
// ---------------------------------------------------------------------------
__global__ __launch_bounds__(256) void preprocess_kernel(
    const float* __restrict__ z, const float* __restrict__ W1,
    const float* __restrict__ W2)
{
    __shared__ float zt[32][68];     // [a][bi_local]
    __shared__ float wt[32][264];    // [a][ci*32 + hi]
    const int bx  = blockIdx.x;
    const int tid = threadIdx.x;

    if (bx < 1024) {
        // ---------------- stage-A ----------------
        const int sub = bx & 63;
        const int oct = sub & 3;           // c0 = oct*8
        const int hg  = sub >> 2;          // h0 = hg*32
        const int bi0 = (bx >> 6) * 64;
        const int c0  = oct * 8, h0 = hg * 32;

        for (int idx = tid; idx < 64 * 32; idx += 256) {
            int r = idx >> 5, a = idx & 31;
            zt[a][r] = z[(bi0 + r) * 32 + a];
        }
        for (int idx = tid; idx < 32 * 256; idx += 256) {
            int a = idx >> 8, col = idx & 255;
            int ci = col >> 5, hi = col & 31;
            wt[a][col] = W1[a * 16384 + (c0 + ci) * 512 + h0 + hi];
        }
        __syncthreads();

        const int tm = tid >> 4;   // 16 groups of 4 bi
        const int tn = tid & 15;   // h pair {h0+tn, h0+tn+16}

        float acc[2][4][8];
#pragma unroll
        for (int u = 0; u < 2; u++)
#pragma unroll
            for (int i = 0; i < 4; i++)
#pragma unroll
                for (int j = 0; j < 8; j++) acc[u][i][j] = 0.f;

#pragma unroll
        for (int k = 0; k < 32; k++) {
            float4 a4 = *(const float4*)&zt[k][tm * 4];
            float av[4] = { a4.x, a4.y, a4.z, a4.w };
            float b0[8], b1[8];
#pragma unroll
            for (int j = 0; j < 8; j++) {
                b0[j] = wt[k][j * 32 + tn];
                b1[j] = wt[k][j * 32 + tn + 16];
            }
#pragma unroll
            for (int i = 0; i < 4; i++)
#pragma unroll
                for (int j = 0; j < 8; j++) {
                    acc[0][i][j] = fmaf(av[i], b0[j], acc[0][i][j]);
                    acc[1][i][j] = fmaf(av[i], b1[j], acc[1][i][j]);
                }
        }

        const int s = oct >> 1, bh = oct & 1;
#pragma unroll
        for (int u = 0; u < 2; u++) {
            const int h   = h0 + tn + u * 16;
            const int chk = h >> 5;
            const int nt  = (h >> 3) & 3;
            const int g   = h & 7;
#pragma unroll
            for (int i = 0; i < 4; i++) {
                const int bi = bi0 + tm * 4 + i;
                uint4 v;
                v.x = ph2(acc[u][i][0], acc[u][i][1]);
                v.y = ph2(acc[u][i][2], acc[u][i][3]);
                v.z = ph2(acc[u][i][4], acc[u][i][5]);
                v.w = ph2(acc[u][i][6], acc[u][i][7]);
                ((uint4*)g_tmph)[(size_t)(bi * 16 + chk) * 128
                                 + ((nt * 2 + s) * 2 + bh) * 8 + g] = v;
            }
        }
    } else if (bx < 1280) {
        // ---------------- pack W2 ----------------
        const int gid  = (bx - 1024) * 256 + tid;   // 65536
        const int bh   = gid & 1;
        const int s    = (gid >> 1) & 1;
        const int lane = (gid >> 2) & 31;
        const int nt   = (gid >> 7) & 31;
        const int chk  = gid >> 12;
        const int h  = chk * 32 + s * 16 + bh * 8 + (lane & 3) * 2;
        const int k2 = nt * 8 + (lane >> 2);
        g_w2h[gid] = ph2(W2[h * 256 + k2], W2[(h + 1) * 256 + k2]);
    } else {
        // ---------------- pack z -----------------
        const int gid  = (bx - 1280) * 256 + tid;   // 16384
        const int r    = gid & 3;
        const int lane = (gid >> 2) & 31;
        const int s    = (gid >> 7) & 1;
        const int tile = gid >> 8;
        const int g = lane >> 2, t = lane & 3;
        const int row = tile * 16 + g + (r & 1) * 8;
        const int col = s * 16 + t * 2 + (r >> 1) * 8;
        g_zh[gid] = ph2(z[row * 32 + col], z[row * 32 + col + 1]);
    }
}

// ---------------------------------------------------------------------------
// Main fused kernel: grid 4096 = (b, i, jt of 4), 128 thr, 3 CTAs/SM.
// Warp w owns j rows [w*16, w*16+16) end-to-end:
//   GEMM1: 16j x 32h chunk (8 MMAs), C-frag -> relu+bias -> fp16 A-frag (regs)
//   GEMM2: 16j x 256k2; nt processed in PAIRS so dependent HMMAs on the same
//          accumulator are 2 apart (A0 nt0, A0 nt1, A1 nt0, A1 nt1).
// smem u32: tmp 2x512 @0, w2 2x4096 @1024; floats: b1@9216 b2@9728 w3@9984.
// ---------------------------------------------------------------------------
#define SM_TOT  10240          // floats = 40960 bytes

__global__ __launch_bounds__(128, 3) void decoder_main_kernel(
    const float* __restrict__ motif,
    const float* __restrict__ b1, const float* __restrict__ b2,
    const float* __restrict__ W3, const float* __restrict__ b3,
    float* __restrict__ out)
{
    extern __shared__ float sm[];
    uint32_t* smu = (uint32_t*)sm;
    const uint32_t s_u32 = (uint32_t)__cvta_generic_to_shared(sm);
    float* s_b1 = sm + 9216;
    float* s_b2 = sm + 9728;
    float* s_w3 = sm + 9984;

    const int cta = blockIdx.x;
    const int jt  = cta & 3;
    const int i   = (cta >> 2) & 255;
    const int b   = cta >> 10;
    const int bi  = b * 256 + i;
    const int j0  = jt * 64;

    const int tid  = threadIdx.x;
    const int w    = tid >> 5;
    const int lane = tid & 31;
    const int g    = lane >> 2;
    const int t    = lane & 3;

    // ---- z A-frags, register-resident (chunk-invariant) ------------------
    uint32_t za[2][4];
    {
        const int tile = ((b * 256 + j0) >> 4) + w;
        const uint4* zf = (const uint4*)g_zh;
#pragma unroll
        for (int s = 0; s < 2; s++) {
            uint4 v = zf[(tile * 2 + s) * 32 + lane];
            za[s][0] = v.x; za[s][1] = v.y; za[s][2] = v.z; za[s][3] = v.w;
        }
    }

    // ---- prologue: async loads of chunk 0 --------------------------------
    {
        const uint4* wsrc = (const uint4*)g_w2h;
#pragma unroll
        for (int r = 0; r < 8; r++)
            cp16(s_u32 + (1024 + (tid + r * 128) * 4) * 4, wsrc + tid + r * 128);
        const uint4* tsrc = (const uint4*)g_tmph + (size_t)bi * 16 * 128;
        cp16(s_u32 + (tid * 4) * 4, tsrc + tid);
        cp_commit();
    }
    for (int idx = tid; idx < 1024; idx += 128) {
        if (idx < 512)       s_b1[idx] = b1[idx];
        else if (idx < 768)  s_b2[idx - 512] = b2[idx - 512];
        else                 s_w3[idx - 768] = W3[idx - 768];
    }

    float acc2[32][4];
#pragma unroll
    for (int nt = 0; nt < 32; nt++)
#pragma unroll
        for (int r = 0; r < 4; r++) acc2[nt][r] = 0.f;

    int buf = 0;
    for (int chk = 0; chk < 16; chk++) {
        cp_wait0();
        __syncthreads();

        if (chk < 15) {
            const int nb = buf ^ 1;
            const uint4* wsrc = (const uint4*)g_w2h + (chk + 1) * 1024;
#pragma unroll
            for (int r = 0; r < 8; r++)
                cp16(s_u32 + (1024 + nb * 4096 + (tid + r * 128) * 4) * 4,
                     wsrc + tid + r * 128);
            const uint4* tsrc = (const uint4*)g_tmph + ((size_t)bi * 16 + chk + 1) * 128;
            cp16(s_u32 + (nb * 512 + tid * 4) * 4, tsrc + tid);
            cp_commit();
        }

        const uint32_t* tb = smu + buf * 512;
        const uint32_t* wb = smu + 1024 + buf * 4096;

        // ---- GEMM1: acc1 = z_rows(w) . tmp^T  (16j x 32h) ----------------
        float acc1[4][4];
#pragma unroll
        for (int nt = 0; nt < 4; nt++)
#pragma unroll
            for (int r = 0; r < 4; r++) acc1[nt][r] = 0.f;

#pragma unroll
        for (int s = 0; s < 2; s++)
#pragma unroll
            for (int nt = 0; nt < 4; nt++) {
                uint32_t b0 = tb[((nt * 2 + s) * 2 + 0) * 32 + lane];
                uint32_t bb = tb[((nt * 2 + s) * 2 + 1) * 32 + lane];
                MMA_F16(acc1[nt], za[s], b0, bb);
            }

        // bias + relu + fp16 pack: C-frag -> A-frag, all in registers
        uint32_t h1h[4][2];
#pragma unroll
        for (int nt = 0; nt < 4; nt++) {
            const float* bb = s_b1 + chk * 32 + nt * 8 + t * 2;
            float v0 = fmaxf(acc1[nt][0] + bb[0], 0.f);
            float v1 = fmaxf(acc1[nt][1] + bb[1], 0.f);
            float v2 = fmaxf(acc1[nt][2] + bb[0], 0.f);
            float v3 = fmaxf(acc1[nt][3] + bb[1], 0.f);
            h1h[nt][0] = ph2(v0, v1);
            h1h[nt][1] = ph2(v2, v3);
        }

        // ---- GEMM2: acc2 += h1(16j) . W2chunk, nt-pair interleaved -------
        {
            uint32_t A0[4] = { h1h[0][0], h1h[0][1], h1h[1][0], h1h[1][1] };
            uint32_t A1[4] = { h1h[2][0], h1h[2][1], h1h[3][0], h1h[3][1] };
            const uint32_t* wp = wb + lane * 4;
#pragma unroll
            for (int np = 0; np < 16; np++) {
                uint4 bv0 = *(const uint4*)&wp[(2 * np) * 128];
                uint4 bv1 = *(const uint4*)&wp[(2 * np + 1) * 128];
                MMA_F16(acc2[2 * np],     A0, bv0.x, bv0.y);
                MMA_F16(acc2[2 * np + 1], A0, bv1.x, bv1.y);
                MMA_F16(acc2[2 * np],     A1, bv0.z, bv0.w);
                MMA_F16(acc2[2 * np + 1], A1, bv1.z, bv1.w);
            }
        }
        buf ^= 1;
    }

    // ---- epilogue: relu(+b2) . W3 (full k2 in-warp), quad-reduce ---------
    float ps0 = 0.f, ps1 = 0.f;
#pragma unroll
    for (int nt = 0; nt < 32; nt++) {
        const int k = nt * 8 + t * 2;
        float h2a = fmaxf(acc2[nt][0] + s_b2[k],     0.f);
        float h2b = fmaxf(acc2[nt][1] + s_b2[k + 1], 0.f);
        float h2c = fmaxf(acc2[nt][2] + s_b2[k],     0.f);
        float h2d = fmaxf(acc2[nt][3] + s_b2[k + 1], 0.f);
        ps0 = fmaf(h2a, s_w3[k], ps0);  ps0 = fmaf(h2b, s_w3[k + 1], ps0);
        ps1 = fmaf(h2c, s_w3[k], ps1);  ps1 = fmaf(h2d, s_w3[k + 1], ps1);
    }
    ps0 += __shfl_xor_sync(0xffffffffu, ps0, 1);
    ps0 += __shfl_xor_sync(0xffffffffu, ps0, 2);
    ps1 += __shfl_xor_sync(0xffffffffu, ps1, 1);
    ps1 += __shfl_xor_sync(0xffffffffu, ps1, 2);

    if (t == 0) {
        const float b3v = b3[0];
        const float mi  = motif[b * 256 + i];
#pragma unroll
        for (int u = 0; u < 2; u++) {
            const int j = j0 + w * 16 + g + u * 8;
            float logit = ((u ? ps1 : ps0) + b3v) * (mi * motif[b * 256 + j]);
            float cmap  = 1.f / (1.f + __expf(-logit));
            size_t base = (size_t)bi * 256 + j;
            out[base]       = cmap;
            out[BNN + base] = logit;
        }
    }
}

// ---------------------------------------------------------------------------
extern "C" void kernel_launch(void* const* d_in, const int* in_sizes, int n_in,
                              void* d_out, int out_size)
{
    const float* z     = (const float*)d_in[0];
    const float* motif = (const float*)d_in[1];
    const float* W1    = (const float*)d_in[3];
    const float* b1    = (const float*)d_in[4];
    const float* W2    = (const float*)d_in[5];
    const float* b2    = (const float*)d_in[6];
    const float* W3    = (const float*)d_in[7];
    const float* b3    = (const float*)d_in[8];
    float* out = (float*)d_out;

    (void)in_sizes; (void)n_in; (void)out_size;

    cudaFuncSetAttribute(decoder_main_kernel,
                         cudaFuncAttributeMaxDynamicSharedMemorySize,
                         SM_TOT * (int)sizeof(float));

    preprocess_kernel<<<1344, 256>>>(z, W1, W2);
    decoder_main_kernel<<<4096, 128, SM_TOT * sizeof(float)>>>(
        motif, b1, b2, W3, b3, out);
}